// round 13
// baseline (speedup 1.0000x reference)
#include <cuda_runtime.h>
#include <float.h>

// Problem constants (fixed by setup_inputs)
#define B_   16
#define L_   128
#define N_   (B_*L_)      // 2048
#define C_   14
#define E_   256
#define K_   9
#define TI_  4            // i-rows per fused block
#define NT_  256          // threads per block (2 atom-groups x 128 columns)
#define FUSED_BLOCKS (B_ * (L_ / TI_))   // 512
#define BIGF 1e10f
#define POISON 3.0e38f

// Output layout (float32, outputs flattened + concatenated in reference order)
#define OFF_H          0u
#define OFF_CTX_KNN    1048576u
#define OFF_CTX_VALID  1085440u
#define OFF_ADJ        1103872u
#define OFF_INT_KNN    1366016u
#define OFF_INT_VALID  1402880u
#define KNN_ROWS       (N_*K_)   // 18432

static __device__ float g_d2[N_ * L_];    // 1 MB d^2 scratch

__device__ __forceinline__ bool is_glob(int s) { return (s == 21) | (s == 22) | (s == 23); }

// ---- packed f32x2 helpers (per-half IEEE identical to scalar sequence) ----
typedef unsigned long long u64t;
__device__ __forceinline__ u64t pack2(float lo, float hi) {
    u64t r; asm("mov.b64 %0, {%1,%2};" : "=l"(r) : "f"(lo), "f"(hi)); return r;
}
__device__ __forceinline__ void unpack2(u64t p, float& lo, float& hi) {
    asm("mov.b64 {%0,%1}, %2;" : "=f"(lo), "=f"(hi) : "l"(p));
}
__device__ __forceinline__ u64t mul2(u64t a, u64t b) {
    u64t r; asm("mul.rn.f32x2 %0, %1, %2;" : "=l"(r) : "l"(a), "l"(b)); return r;
}
__device__ __forceinline__ u64t add2(u64t a, u64t b) {
    u64t r; asm("add.rn.f32x2 %0, %1, %2;" : "=l"(r) : "l"(a), "l"(b)); return r;
}
__device__ __forceinline__ u64t fma2(u64t a, u64t b, u64t c) {
    u64t r; asm("fma.rn.f32x2 %0, %1, %2, %3;" : "=l"(r) : "l"(a), "l"(b), "l"(c)); return r;
}

struct SmemFused {
    __align__(16) u64t sdup[TI_ * C_ * 4];  // {v,v} broadcast operands: x0,x1,x2,sq per (ii,c)
    float sraw[42 * 129];         // [r=c*3+d][j], pitch 129 (transpose pad)
    float spart[2][TI_][L_];      // partial min d2 per atom-group
    int   sS[L_], sSeg[L_];
};
struct SmemEmbed {
    int sA[C_], sAP[C_];
};
union SmemAll { SmemFused f; SmemEmbed e; };

// ---------------------------------------------------------------------------
// Kernel A; blockIdx < FUSED_BLOCKS -> triangular dist + adj, else -> embed.
// ---------------------------------------------------------------------------
__global__ void __launch_bounds__(NT_, 4) mono_kernel(
        const float* __restrict__ X, const int* __restrict__ AP,
        const int* __restrict__ S, const int* __restrict__ seg,
        const int* __restrict__ RP, const int* __restrict__ A,
        const float* __restrict__ res_e, const float* __restrict__ atom_e,
        const float* __restrict__ atom_pe,
        float* __restrict__ out)
{
    __shared__ SmemAll sm;
    const int t = threadIdx.x;

    if (blockIdx.x >= FUSED_BLOCKS) {
        // ================= EMBED: one residue, 256 threads = 256 channels ===
        const int n = blockIdx.x - FUSED_BLOCKS;
        if (t < C_) { sm.e.sA[t] = A[n*C_ + t]; sm.e.sAP[t] = AP[n*C_ + t]; }
        __syncthreads();
        int cnt = 0;
        #pragma unroll
        for (int c = 0; c < C_; c++) cnt += (sm.e.sAP[c] != 0);
        float den = (float)cnt + 1e-10f;

        int   s  = S[n];
        float rp = (float)RP[n];
        int   e  = t;
        int   i2 = e >> 1;
        float inv = exp2f(-(float)i2 * (13.287712379549449f / 128.0f));
        float ang = rp * inv;
        float pos = (e & 1) ? __cosf(ang) : __sinf(ang);
        out[OFF_H + (unsigned)n * 512u + e] = res_e[s * E_ + e] + pos;

        float acc = 0.0f;
        #pragma unroll
        for (int c = 0; c < C_; c++) {
            int ap = sm.e.sAP[c];
            if (ap != 0) acc += atom_e[sm.e.sA[c] * E_ + e] + atom_pe[ap * E_ + e];
        }
        out[OFF_H + (unsigned)n * 512u + 256u + e] = acc / den;
        return;
    }

    // ================= TRIANGULAR dist + adj ================================
    const int b  = blockIdx.x / (L_ / TI_);
    const int i0 = (blockIdx.x % (L_ / TI_)) * TI_;
    const int g  = t >> 7;          // atom-group: 0 -> atoms 0..7, 1 -> atoms 8..13
    const int j  = t & 127;         // column
    const bool active = (j >= i0);  // triangular: only columns j >= i0

    // --- staging: coalesced read of whole batch coords -> padded transpose ---
    const float* Xb = X + (size_t)b * L_ * C_ * 3;
    #pragma unroll
    for (int k = 0; k < 21; k++) {
        int idx = k * NT_ + t;               // 21*256 = 5376 = L_*C_*3
        int jj  = idx / 42;
        int r   = idx - jj * 42;
        sm.f.sraw[r * 129 + jj] = Xb[idx];
    }
    if (t < L_) {
        sm.f.sS[t]   = S[b * L_ + t];
        sm.f.sSeg[t] = seg[b * L_ + t];
    }
    __syncthreads();

    // --- pack: own 4 atom-pairs into packed registers; owners also fill sdup ---
    u64t y0p[4], y1p[4], y2p[4], sjp[4];
    if (active) {
        const int cbase = g * 8;
        const int* apRow = AP + ((size_t)b * L_ + j) * C_;
        const unsigned iio = (unsigned)(j - i0);
        const bool owner = iio < TI_;
        #pragma unroll
        for (int p = 0; p < 4; p++) {
            float a0l=0.f,a1l=0.f,a2l=0.f,sql=POISON;
            float a0h=0.f,a1h=0.f,a2h=0.f,sqh=POISON;
            int c0 = cbase + 2*p, c1 = c0 + 1;
            if (c0 < C_) {
                a0l = sm.f.sraw[(3*c0+0)*129 + j];
                a1l = sm.f.sraw[(3*c0+1)*129 + j];
                a2l = sm.f.sraw[(3*c0+2)*129 + j];
                float sq = (a0l*a0l + a1l*a1l) + a2l*a2l;
                sql = (apRow[c0] != 0) ? sq : POISON;
                if (owner) {
                    u64t* d = &sm.f.sdup[(iio * C_ + c0) * 4];
                    d[0] = pack2(a0l,a0l); d[1] = pack2(a1l,a1l);
                    d[2] = pack2(a2l,a2l); d[3] = pack2(sql,sql);
                }
            }
            if (c1 < C_) {
                a0h = sm.f.sraw[(3*c1+0)*129 + j];
                a1h = sm.f.sraw[(3*c1+1)*129 + j];
                a2h = sm.f.sraw[(3*c1+2)*129 + j];
                float sq = (a0h*a0h + a1h*a1h) + a2h*a2h;
                sqh = (apRow[c1] != 0) ? sq : POISON;
                if (owner) {
                    u64t* d = &sm.f.sdup[(iio * C_ + c1) * 4];
                    d[0] = pack2(a0h,a0h); d[1] = pack2(a1h,a1h);
                    d[2] = pack2(a2h,a2h); d[3] = pack2(sqh,sqh);
                }
            }
            y0p[p] = pack2(a0l, a0h);
            y1p[p] = pack2(a1l, a1h);
            y2p[p] = pack2(a2l, a2h);
            sjp[p] = pack2(sql, sqh);
        }
    }
    __syncthreads();

    // --- hot loop: partial min over this group's atom pairs (j >= i0 only) ---
    const u64t negtwo = pack2(-2.0f, -2.0f);
    if (active) {
        #pragma unroll 2
        for (int ii = 0; ii < TI_; ii++) {
            float b0 = FLT_MAX, b1 = FLT_MAX, b2 = FLT_MAX, b3 = FLT_MAX;
            const ulonglong2* dup = (const ulonglong2*)&sm.f.sdup[ii * C_ * 4];
            #pragma unroll
            for (int c = 0; c < C_; c++) {
                ulonglong2 dA = dup[c*2 + 0];    // {xi0p, xi1p}  LDS.128 broadcast
                ulonglong2 dB = dup[c*2 + 1];    // {xi2p, sqcp}
                u64t xi0p = dA.x, xi1p = dA.y, xi2p = dB.x, sqcp = dB.y;
                #pragma unroll
                for (int p = 0; p < 4; p += 2) {
                    {
                        u64t dot = fma2(xi2p, y2p[p], fma2(xi1p, y1p[p], mul2(xi0p, y0p[p])));
                        u64t d2  = fma2(dot, negtwo, add2(sqcp, sjp[p]));
                        float lo, hi;
                        unpack2(d2, lo, hi);
                        b0 = fminf(b0, lo);
                        b1 = fminf(b1, hi);
                    }
                    {
                        u64t dot = fma2(xi2p, y2p[p+1], fma2(xi1p, y1p[p+1], mul2(xi0p, y0p[p+1])));
                        u64t d2  = fma2(dot, negtwo, add2(sqcp, sjp[p+1]));
                        float lo, hi;
                        unpack2(d2, lo, hi);
                        b2 = fminf(b2, lo);
                        b3 = fminf(b3, hi);
                    }
                }
            }
            sm.f.spart[g][ii][j] = fminf(fminf(b0, b1), fminf(b2, b3));
        }
    }

    // --- adj rows (all threads): thread (g, j) handles rows i0+2g, i0+2g+1 ---
    {
        bool gj = is_glob(sm.f.sS[j]);
        int  segj = sm.f.sSeg[j];
        #pragma unroll
        for (int r2 = 0; r2 < 2; r2++) {
            int i = i0 + g * 2 + r2;
            bool gi = is_glob(sm.f.sS[i]);
            bool same = (sm.f.sSeg[i] == segj);
            bool ns   = (i != j);
            bool gn = same && (gi || gj) && ns;
            bool gg = gi && gj && ns;
            int  d  = i - j; if (d < 0) d = -d;
            bool sme = (d == 1) && !gi && !gj && (sm.f.sSeg[i] != 1);
            out[OFF_ADJ + ((unsigned)(b * L_ + i)) * L_ + j] = (gn || gg || sme) ? 1.0f : 0.0f;
        }
    }
    __syncthreads();

    // --- combine partials, write d2 row segment + mirrored column segment ---
    if (t < L_ && t >= i0) {
        float dv[TI_];
        #pragma unroll
        for (int ii = 0; ii < TI_; ii++) {
            float d2 = fminf(sm.f.spart[0][ii][t], sm.f.spart[1][ii][t]);
            dv[ii] = d2;
            g_d2[((unsigned)(b * L_ + i0 + ii)) * L_ + t] = d2;     // direct
        }
        *(float4*)&g_d2[((unsigned)(b * L_ + t)) * L_ + i0] =       // mirror
            make_float4(dv[0], dv[1], dv[2], dv[3]);
    }
}

// ---------------------------------------------------------------------------
// Kernel B: KNN. One warp per row; both mask types per warp.
// redux-min on float bits (order-preserving for >=0) + redux-min argmin index
// reproduces top_k's smaller-index tie-break exactly.
// ---------------------------------------------------------------------------
__device__ __forceinline__ void select9(unsigned u0, unsigned u1, unsigned u2, unsigned u3,
                                        int r, int b, unsigned offK, unsigned offV,
                                        int lane, unsigned BIGB, float* __restrict__ out)
{
    #pragma unroll
    for (int k = 0; k < K_; k++) {
        unsigned m  = min(min(u0, u1), min(u2, u3));
        unsigned w  = __reduce_min_sync(0xffffffffu, m);
        unsigned jc = 256u;
        if (u3 == w) jc = (unsigned)lane + 96u;
        if (u2 == w) jc = (unsigned)lane + 64u;
        if (u1 == w) jc = (unsigned)lane + 32u;
        if (u0 == w) jc = (unsigned)lane;
        unsigned jw = __reduce_min_sync(0xffffffffu, jc);
        unsigned s  = jw >> 5;
        bool own = (jc == jw);
        u0 = (own && s == 0u) ? 0xFFFFFFFFu : u0;
        u1 = (own && s == 1u) ? 0xFFFFFFFFu : u1;
        u2 = (own && s == 2u) ? 0xFFFFFFFFu : u2;
        u3 = (own && s == 3u) ? 0xFFFFFFFFu : u3;
        if (lane == 0) {
            bool valid = w < BIGB;
            out[offK + (unsigned)r * K_ + k]            = valid ? (float)r            : -1.0f;
            out[offK + KNN_ROWS + (unsigned)r * K_ + k] = valid ? (float)(b*L_ + (int)jw) : -1.0f;
            out[offV + (unsigned)r * K_ + k]            = valid ? 1.0f : 0.0f;
        }
    }
}

__global__ void __launch_bounds__(256) knn_kernel(const int* __restrict__ S,
                                                  const int* __restrict__ seg,
                                                  float* __restrict__ out)
{
    const int lane = threadIdx.x & 31;
    const int r = blockIdx.x * 8 + (threadIdx.x >> 5);    // row 0..2047
    const int b = r >> 7, i = r & 127;
    const unsigned BIGB = __float_as_uint(BIGF);

    bool gi = is_glob(S[r]);
    int  si = seg[r];

    unsigned uc[4], ui[4];
    #pragma unroll
    for (int s2 = 0; s2 < 4; s2++) {
        int jj = lane + 32 * s2;
        int nj = b * L_ + jj;
        bool gj   = is_glob(S[nj]);
        bool same = (seg[nj] == si);
        float d2 = g_d2[(unsigned)r * L_ + jj];
        float dv = sqrtf(fmaxf(d2, 0.0f));
        unsigned ub = __float_as_uint(dv);
        bool mc = same && !gi && !gj && (jj != i);
        bool mo = !same && !gi && !gj;
        uc[s2] = mc ? ub : BIGB;
        ui[s2] = mo ? ub : BIGB;
    }
    select9(uc[0], uc[1], uc[2], uc[3], r, b, OFF_CTX_KNN, OFF_CTX_VALID, lane, BIGB, out);
    select9(ui[0], ui[1], ui[2], ui[3], r, b, OFF_INT_KNN, OFF_INT_VALID, lane, BIGB, out);
}

// ---------------------------------------------------------------------------
extern "C" void kernel_launch(void* const* d_in, const int* in_sizes, int n_in,
                              void* d_out, int out_size)
{
    const int*   S   = (const int*)  d_in[0];
    const int*   RP  = (const int*)  d_in[1];
    const int*   A   = (const int*)  d_in[2];
    const int*   AP  = (const int*)  d_in[3];
    const float* X   = (const float*)d_in[4];
    const int*   seg = (const int*)  d_in[5];
    const float* re  = (const float*)d_in[6];
    const float* ae  = (const float*)d_in[7];
    const float* ape = (const float*)d_in[8];
    float* out = (float*)d_out;

    mono_kernel<<<FUSED_BLOCKS + N_, NT_>>>(X, AP, S, seg, RP, A, re, ae, ape, out);
    knn_kernel<<<N_ / 8, 256>>>(S, seg, out);
}

// round 14
// speedup vs baseline: 1.0654x; 1.0654x over previous
#include <cuda_runtime.h>
#include <float.h>

// Problem constants (fixed by setup_inputs)
#define B_   16
#define L_   128
#define N_   (B_*L_)      // 2048
#define C_   14
#define E_   256
#define K_   9
#define TI_  4            // i-rows per fused block
#define NT_  256          // threads per block (2 atom-groups x 128 columns)
#define FUSED_BLOCKS (B_ * (L_ / TI_))   // 512
#define EMBED_BLOCKS (N_ / 2)            // 1024
#define BIGF 1e10f
#define POISON 3.0e38f

// Output layout (float32, outputs flattened + concatenated in reference order)
#define OFF_H          0u
#define OFF_CTX_KNN    1048576u
#define OFF_CTX_VALID  1085440u
#define OFF_ADJ        1103872u
#define OFF_INT_KNN    1366016u
#define OFF_INT_VALID  1402880u
#define KNN_ROWS       (N_*K_)   // 18432

static __device__ float g_d2[N_ * L_];    // 1 MB d^2 scratch

__device__ __forceinline__ bool is_glob(int s) { return (s == 21) | (s == 22) | (s == 23); }

// ---- packed f32x2 helpers (per-half IEEE identical to scalar sequence) ----
typedef unsigned long long u64t;
__device__ __forceinline__ u64t pack2(float lo, float hi) {
    u64t r; asm("mov.b64 %0, {%1,%2};" : "=l"(r) : "f"(lo), "f"(hi)); return r;
}
__device__ __forceinline__ void unpack2(u64t p, float& lo, float& hi) {
    asm("mov.b64 {%0,%1}, %2;" : "=f"(lo), "=f"(hi) : "l"(p));
}
__device__ __forceinline__ u64t mul2(u64t a, u64t b) {
    u64t r; asm("mul.rn.f32x2 %0, %1, %2;" : "=l"(r) : "l"(a), "l"(b)); return r;
}
__device__ __forceinline__ u64t add2(u64t a, u64t b) {
    u64t r; asm("add.rn.f32x2 %0, %1, %2;" : "=l"(r) : "l"(a), "l"(b)); return r;
}
__device__ __forceinline__ u64t fma2(u64t a, u64t b, u64t c) {
    u64t r; asm("fma.rn.f32x2 %0, %1, %2, %3;" : "=l"(r) : "l"(a), "l"(b), "l"(c)); return r;
}

struct SmemFused {
    __align__(16) u64t sdup[TI_ * C_ * 4];  // {v,v} broadcast operands: x0,x1,x2,sq per (ii,c)
    float sraw[42 * 129];         // [r=c*3+d][j], pitch 129 (transpose pad)
    float spart[2][TI_][L_];      // partial min d2 per atom-group
    int   sS[L_], sSeg[L_];
};
struct SmemEmbed {
    int sA[2][C_], sAP[2][C_];
};
union SmemAll { SmemFused f; SmemEmbed e; };

// ---------------------------------------------------------------------------
// Kernel A; blockIdx < FUSED_BLOCKS -> triangular dist + adj, else -> embed x2.
// ---------------------------------------------------------------------------
__global__ void __launch_bounds__(NT_, 4) mono_kernel(
        const float* __restrict__ X, const int* __restrict__ AP,
        const int* __restrict__ S, const int* __restrict__ seg,
        const int* __restrict__ RP, const int* __restrict__ A,
        const float* __restrict__ res_e, const float* __restrict__ atom_e,
        const float* __restrict__ atom_pe,
        float* __restrict__ out)
{
    __shared__ SmemAll sm;
    const int t = threadIdx.x;

    if (blockIdx.x >= FUSED_BLOCKS) {
        // ========== EMBED: 2 residues/block, thread = channel pair ==========
        const int nb   = blockIdx.x - FUSED_BLOCKS;
        const int half = t >> 7;
        const int e    = t & 127;                 // channel-pair index 0..127
        const int n    = nb * 2 + half;
        if (e < C_) { sm.e.sA[half][e] = A[n*C_ + e]; sm.e.sAP[half][e] = AP[n*C_ + e]; }
        __syncthreads();
        int cnt = 0;
        #pragma unroll
        for (int c = 0; c < C_; c++) cnt += (sm.e.sAP[half][c] != 0);
        float den = (float)cnt + 1e-10f;

        int   s  = S[n];
        float rp = (float)RP[n];
        float inv = exp2f(-(float)e * (13.287712379549449f / 128.0f));
        float ang = rp * inv;
        float sv, cv;
        __sincosf(ang, &sv, &cv);
        float2 re2 = *(const float2*)&res_e[s * E_ + 2*e];
        float2 o0; o0.x = re2.x + sv; o0.y = re2.y + cv;
        *(float2*)&out[OFF_H + (unsigned)n * 512u + 2*e] = o0;

        float accx = 0.0f, accy = 0.0f;
        #pragma unroll
        for (int c = 0; c < C_; c++) {
            int ap = sm.e.sAP[half][c];
            if (ap != 0) {
                float2 ae2 = *(const float2*)&atom_e [sm.e.sA[half][c] * E_ + 2*e];
                float2 pe2 = *(const float2*)&atom_pe[ap * E_ + 2*e];
                accx += ae2.x + pe2.x;
                accy += ae2.y + pe2.y;
            }
        }
        float2 o1; o1.x = accx / den; o1.y = accy / den;
        *(float2*)&out[OFF_H + (unsigned)n * 512u + 256u + 2*e] = o1;
        return;
    }

    // ================= TRIANGULAR dist + adj ================================
    const int b  = blockIdx.x / (L_ / TI_);
    const int i0 = (blockIdx.x % (L_ / TI_)) * TI_;
    const int g  = t >> 7;          // atom-group: 0 -> atoms 0..7, 1 -> atoms 8..13
    const int j  = t & 127;         // column
    const bool active = (j >= i0);  // triangular: only columns j >= i0

    // --- staging: coalesced read of whole batch coords -> padded transpose ---
    const float* Xb = X + (size_t)b * L_ * C_ * 3;
    #pragma unroll
    for (int k = 0; k < 21; k++) {
        int idx = k * NT_ + t;               // 21*256 = 5376 = L_*C_*3
        int jj  = idx / 42;
        int r   = idx - jj * 42;
        sm.f.sraw[r * 129 + jj] = Xb[idx];
    }
    if (t < L_) {
        sm.f.sS[t]   = S[b * L_ + t];
        sm.f.sSeg[t] = seg[b * L_ + t];
    }
    __syncthreads();

    // --- pack: own 4 atom-pairs into packed registers; owners also fill sdup ---
    u64t y0p[4], y1p[4], y2p[4], sjp[4];
    if (active) {
        const int cbase = g * 8;
        const int* apRow = AP + ((size_t)b * L_ + j) * C_;
        const unsigned iio = (unsigned)(j - i0);
        const bool owner = iio < TI_;
        #pragma unroll
        for (int p = 0; p < 4; p++) {
            float a0l=0.f,a1l=0.f,a2l=0.f,sql=POISON;
            float a0h=0.f,a1h=0.f,a2h=0.f,sqh=POISON;
            int c0 = cbase + 2*p, c1 = c0 + 1;
            if (c0 < C_) {
                a0l = sm.f.sraw[(3*c0+0)*129 + j];
                a1l = sm.f.sraw[(3*c0+1)*129 + j];
                a2l = sm.f.sraw[(3*c0+2)*129 + j];
                float sq = (a0l*a0l + a1l*a1l) + a2l*a2l;
                sql = (apRow[c0] != 0) ? sq : POISON;
                if (owner) {
                    u64t* d = &sm.f.sdup[(iio * C_ + c0) * 4];
                    d[0] = pack2(a0l,a0l); d[1] = pack2(a1l,a1l);
                    d[2] = pack2(a2l,a2l); d[3] = pack2(sql,sql);
                }
            }
            if (c1 < C_) {
                a0h = sm.f.sraw[(3*c1+0)*129 + j];
                a1h = sm.f.sraw[(3*c1+1)*129 + j];
                a2h = sm.f.sraw[(3*c1+2)*129 + j];
                float sq = (a0h*a0h + a1h*a1h) + a2h*a2h;
                sqh = (apRow[c1] != 0) ? sq : POISON;
                if (owner) {
                    u64t* d = &sm.f.sdup[(iio * C_ + c1) * 4];
                    d[0] = pack2(a0h,a0h); d[1] = pack2(a1h,a1h);
                    d[2] = pack2(a2h,a2h); d[3] = pack2(sqh,sqh);
                }
            }
            y0p[p] = pack2(a0l, a0h);
            y1p[p] = pack2(a1l, a1h);
            y2p[p] = pack2(a2l, a2h);
            sjp[p] = pack2(sql, sqh);
        }
    }
    __syncthreads();

    // --- hot loop: partial min over this group's atom pairs (j >= i0 only) ---
    const u64t negtwo = pack2(-2.0f, -2.0f);
    if (active) {
        #pragma unroll 2
        for (int ii = 0; ii < TI_; ii++) {
            float b0 = FLT_MAX, b1 = FLT_MAX, b2 = FLT_MAX, b3 = FLT_MAX;
            const ulonglong2* dup = (const ulonglong2*)&sm.f.sdup[ii * C_ * 4];
            #pragma unroll
            for (int c = 0; c < C_; c++) {
                ulonglong2 dA = dup[c*2 + 0];    // {xi0p, xi1p}  LDS.128 broadcast
                ulonglong2 dB = dup[c*2 + 1];    // {xi2p, sqcp}
                u64t xi0p = dA.x, xi1p = dA.y, xi2p = dB.x, sqcp = dB.y;
                #pragma unroll
                for (int p = 0; p < 4; p += 2) {
                    {
                        u64t dot = fma2(xi2p, y2p[p], fma2(xi1p, y1p[p], mul2(xi0p, y0p[p])));
                        u64t d2  = fma2(dot, negtwo, add2(sqcp, sjp[p]));
                        float lo, hi;
                        unpack2(d2, lo, hi);
                        b0 = fminf(b0, lo);
                        b1 = fminf(b1, hi);
                    }
                    {
                        u64t dot = fma2(xi2p, y2p[p+1], fma2(xi1p, y1p[p+1], mul2(xi0p, y0p[p+1])));
                        u64t d2  = fma2(dot, negtwo, add2(sqcp, sjp[p+1]));
                        float lo, hi;
                        unpack2(d2, lo, hi);
                        b2 = fminf(b2, lo);
                        b3 = fminf(b3, hi);
                    }
                }
            }
            sm.f.spart[g][ii][j] = fminf(fminf(b0, b1), fminf(b2, b3));
        }
    }

    // --- adj rows (all threads): thread (g, j) handles rows i0+2g, i0+2g+1 ---
    {
        bool gj = is_glob(sm.f.sS[j]);
        int  segj = sm.f.sSeg[j];
        #pragma unroll
        for (int r2 = 0; r2 < 2; r2++) {
            int i = i0 + g * 2 + r2;
            bool gi = is_glob(sm.f.sS[i]);
            bool same = (sm.f.sSeg[i] == segj);
            bool ns   = (i != j);
            bool gn = same && (gi || gj) && ns;
            bool gg = gi && gj && ns;
            int  d  = i - j; if (d < 0) d = -d;
            bool sme = (d == 1) && !gi && !gj && (sm.f.sSeg[i] != 1);
            out[OFF_ADJ + ((unsigned)(b * L_ + i)) * L_ + j] = (gn || gg || sme) ? 1.0f : 0.0f;
        }
    }
    __syncthreads();

    // --- combine partials, write d2 row segment + mirrored column segment ---
    if (t < L_ && t >= i0) {
        float dv[TI_];
        #pragma unroll
        for (int ii = 0; ii < TI_; ii++) {
            float d2 = fminf(sm.f.spart[0][ii][t], sm.f.spart[1][ii][t]);
            dv[ii] = d2;
            g_d2[((unsigned)(b * L_ + i0 + ii)) * L_ + t] = d2;     // direct
        }
        *(float4*)&g_d2[((unsigned)(b * L_ + t)) * L_ + i0] =       // mirror
            make_float4(dv[0], dv[1], dv[2], dv[3]);
    }
}

// ---------------------------------------------------------------------------
// Kernel B: KNN. One warp per (row, type): 4096 warps, grid 512.
// redux-min on float bits (order-preserving for >=0) + redux-min argmin index
// reproduces top_k's smaller-index tie-break exactly (validated in R13).
// ---------------------------------------------------------------------------
__global__ void __launch_bounds__(256) knn_kernel(const int* __restrict__ S,
                                                  const int* __restrict__ seg,
                                                  float* __restrict__ out)
{
    const int lane = threadIdx.x & 31;
    const int w    = blockIdx.x * 8 + (threadIdx.x >> 5);   // 0..4095
    const int type = w & 1;
    const int r    = w >> 1;                                 // row 0..2047
    const int b    = r >> 7, i = r & 127;
    const unsigned BIGB = __float_as_uint(BIGF);

    bool gi = is_glob(S[r]);
    int  si = seg[r];

    unsigned u0, u1, u2, u3;
    {
        unsigned uu[4];
        #pragma unroll
        for (int s2 = 0; s2 < 4; s2++) {
            int jj = lane + 32 * s2;
            int nj = b * L_ + jj;
            bool gj   = is_glob(S[nj]);
            bool same = (seg[nj] == si);
            float d2 = g_d2[(unsigned)r * L_ + jj];
            float dv = sqrtf(fmaxf(d2, 0.0f));
            unsigned ub = __float_as_uint(dv);
            bool m;
            if (type == 0) m = same && !gi && !gj && (jj != i);
            else           m = !same && !gi && !gj;
            uu[s2] = m ? ub : BIGB;
        }
        u0 = uu[0]; u1 = uu[1]; u2 = uu[2]; u3 = uu[3];
    }

    const unsigned offK = type ? OFF_INT_KNN   : OFF_CTX_KNN;
    const unsigned offV = type ? OFF_INT_VALID : OFF_CTX_VALID;

    #pragma unroll
    for (int k = 0; k < K_; k++) {
        unsigned m  = min(min(u0, u1), min(u2, u3));
        unsigned wmin = __reduce_min_sync(0xffffffffu, m);
        unsigned jc = 256u;
        if (u3 == wmin) jc = (unsigned)lane + 96u;
        if (u2 == wmin) jc = (unsigned)lane + 64u;
        if (u1 == wmin) jc = (unsigned)lane + 32u;
        if (u0 == wmin) jc = (unsigned)lane;
        unsigned jw = __reduce_min_sync(0xffffffffu, jc);
        unsigned s  = jw >> 5;
        bool own = (jc == jw);
        u0 = (own && s == 0u) ? 0xFFFFFFFFu : u0;
        u1 = (own && s == 1u) ? 0xFFFFFFFFu : u1;
        u2 = (own && s == 2u) ? 0xFFFFFFFFu : u2;
        u3 = (own && s == 3u) ? 0xFFFFFFFFu : u3;
        if (lane == 0) {
            bool valid = wmin < BIGB;
            out[offK + (unsigned)r * K_ + k]            = valid ? (float)r               : -1.0f;
            out[offK + KNN_ROWS + (unsigned)r * K_ + k] = valid ? (float)(b*L_ + (int)jw) : -1.0f;
            out[offV + (unsigned)r * K_ + k]            = valid ? 1.0f : 0.0f;
        }
    }
}

// ---------------------------------------------------------------------------
extern "C" void kernel_launch(void* const* d_in, const int* in_sizes, int n_in,
                              void* d_out, int out_size)
{
    const int*   S   = (const int*)  d_in[0];
    const int*   RP  = (const int*)  d_in[1];
    const int*   A   = (const int*)  d_in[2];
    const int*   AP  = (const int*)  d_in[3];
    const float* X   = (const float*)d_in[4];
    const int*   seg = (const int*)  d_in[5];
    const float* re  = (const float*)d_in[6];
    const float* ae  = (const float*)d_in[7];
    const float* ape = (const float*)d_in[8];
    float* out = (float*)d_out;

    mono_kernel<<<FUSED_BLOCKS + EMBED_BLOCKS, NT_>>>(X, AP, S, seg, RP, A, re, ae, ape, out);
    knn_kernel<<<N_ * 2 / 8, 256>>>(S, seg, out);
}